// round 13
// baseline (speedup 1.0000x reference)
#include <cuda_runtime.h>
#include <cstdint>

#define NN 50000
#define EE 800000
#define DD 64

// ---------------- device scratch (static: no allocation allowed) ----------------
__device__ int g_flag64;
__device__ int g_src[EE];
__device__ int g_dst[EE];
__device__ int g_deg[NN];
__device__ int g_rowptr[NN + 1];
__device__ int g_tail[NN];
__device__ int g_srcsorted[EE];
__device__ float g_h[NN * DD];
__device__ float g_hpre[NN * DD];
__device__ float g_xproj[NN * DD];
__device__ unsigned char g_keep[NN];
__device__ float g_bnsum[DD];
__device__ float g_bnsq[DD];
__device__ float g_mu[DD];
__device__ float g_inv[DD];

// ---------------- threefry2x32 (matches JAX exactly) ----------------
__host__ __device__ __forceinline__ void tf2x32(uint32_t k0, uint32_t k1,
                                                uint32_t x0, uint32_t x1,
                                                uint32_t& o0, uint32_t& o1) {
    uint32_t ks2 = k0 ^ k1 ^ 0x1BD11BDAu;
    x0 += k0; x1 += k1;
#define TF_RND(r) { x0 += x1; x1 = (x1 << (r)) | (x1 >> (32 - (r))); x1 ^= x0; }
    TF_RND(13) TF_RND(15) TF_RND(26) TF_RND(6)   x0 += k1;  x1 += ks2 + 1u;
    TF_RND(17) TF_RND(29) TF_RND(16) TF_RND(24)  x0 += ks2; x1 += k0 + 2u;
    TF_RND(13) TF_RND(15) TF_RND(26) TF_RND(6)   x0 += k0;  x1 += k1 + 3u;
    TF_RND(17) TF_RND(29) TF_RND(16) TF_RND(24)  x0 += k1;  x1 += ks2 + 4u;
    TF_RND(13) TF_RND(15) TF_RND(26) TF_RND(6)   x0 += ks2; x1 += k0 + 5u;
#undef TF_RND
    o0 = x0; o1 = x1;
}

__device__ __forceinline__ unsigned keepbit(uint32_t bits) {
    // JAX uniform: bitcast(bits>>9 | 0x3f800000) - 1.0  in [0,1); drop iff u < p
    float u = __uint_as_float((bits >> 9) | 0x3f800000u) - 1.0f;
    return (u < 0.2f) ? 0u : 1u;
}

__device__ __forceinline__ float mishf(float x) {
    // softplus via logaddexp(x,0) (numerically stable, matches jax.nn.softplus)
    float sp = fmaxf(x, 0.0f) + log1pf(expf(-fabsf(x)));
    return x * tanhf(sp);
}

// ---------------- preprocessing kernels ----------------
__global__ void k_detect(const unsigned long long* ei) {
    __shared__ int any;
    if (threadIdx.x == 0) any = 0;
    __syncthreads();
    int nz = 0;
    for (int q = 0; q < 4; q++) {
        unsigned long long v = ei[threadIdx.x * 4 + q];
        if ((v >> 32) != 0ull) nz = 1;
    }
    if (nz) any = 1;
    __syncthreads();
    if (threadIdx.x == 0) g_flag64 = any ? 0 : 1;  // all-high-zero => genuine int64
}

__global__ void k_zerodeg() {
    int i = blockIdx.x * blockDim.x + threadIdx.x;
    if (i < NN) g_deg[i] = 0;
}

__global__ void k_convert(const void* ei) {
    int e = blockIdx.x * blockDim.x + threadIdx.x;
    if (e >= EE) return;
    int s, d;
    if (g_flag64) {
        const long long* p = (const long long*)ei;
        s = (int)p[e]; d = (int)p[EE + e];
    } else {
        const int* p = (const int*)ei;
        s = p[e]; d = p[EE + e];
    }
    g_src[e] = s; g_dst[e] = d;
    atomicAdd(&g_deg[d], 1);
}

__global__ void k_scan() {   // single block, 1024 threads: exclusive scan of deg
    __shared__ int sw[32];
    __shared__ int s_running;
    int tid = threadIdx.x, lane = tid & 31, wid = tid >> 5;
    if (tid == 0) s_running = 0;
    __syncthreads();
    for (int base = 0; base < NN; base += 1024) {
        int i = base + tid;
        int orig = (i < NN) ? g_deg[i] : 0;
        int v = orig;
#pragma unroll
        for (int d = 1; d < 32; d <<= 1) {
            int t = __shfl_up_sync(0xffffffffu, v, d);
            if (lane >= d) v += t;
        }
        if (lane == 31) sw[wid] = v;
        __syncthreads();
        if (wid == 0) {
            int w = sw[lane];
#pragma unroll
            for (int d = 1; d < 32; d <<= 1) {
                int t = __shfl_up_sync(0xffffffffu, w, d);
                if (lane >= d) w += t;
            }
            sw[lane] = w;
        }
        __syncthreads();
        int add = (wid ? sw[wid - 1] : 0) + s_running;
        int excl = v - orig + add;
        if (i < NN) { g_rowptr[i] = excl; g_tail[i] = excl; }
        int total = sw[31];
        __syncthreads();
        if (tid == 0) s_running += total;
        __syncthreads();
    }
    if (tid == 0) g_rowptr[NN] = s_running;
}

__global__ void k_scatter() {
    int e = blockIdx.x * blockDim.x + threadIdx.x;
    if (e >= EE) return;
    int d = g_dst[e];
    int p = atomicAdd(&g_tail[d], 1);
    g_srcsorted[p] = g_src[e];
}

// ---------------- x_proj: mish(x@W1+b1)@W2+b2 ; 4 rows per warp ----------------
__global__ void __launch_bounds__(256) k_xproj(const float* __restrict__ x,
                                               const float* __restrict__ W1, const float* __restrict__ b1,
                                               const float* __restrict__ W2, const float* __restrict__ b2) {
    __shared__ float sW1[DD * DD], sW2[DD * DD], sb1[DD], sb2[DD];
    __shared__ float sS[8][4][DD];
    int tid = threadIdx.x, lane = tid & 31, w = tid >> 5;
    for (int i = tid; i < DD * DD; i += 256) { sW1[i] = W1[i]; sW2[i] = W2[i]; }
    if (tid < DD) { sb1[tid] = b1[tid]; sb2[tid] = b2[tid]; }
    __syncthreads();
    const float2* sW1v = (const float2*)sW1;
    const float2* sW2v = (const float2*)sW2;
    int f0 = lane * 2;
    int gw = blockIdx.x * 8 + w;
    int stride = gridDim.x * 8 * 4;
    for (int base = gw * 4; base < NN; base += stride) {
#pragma unroll
        for (int q = 0; q < 4; q++) {
            int n = base + q;
            float2 v = make_float2(0.f, 0.f);
            if (n < NN) v = *(const float2*)(x + (size_t)n * DD + f0);
            *(float2*)&sS[w][q][f0] = v;
        }
        __syncwarp();
        float bx = sb1[f0], by = sb1[f0 + 1];
        float2 c0 = {bx, by}, c1 = {bx, by}, c2 = {bx, by}, c3 = {bx, by};
#pragma unroll 8
        for (int j = 0; j < DD; j++) {
            float2 wp = sW1v[j * 32 + lane];
            float g0 = sS[w][0][j], g1 = sS[w][1][j], g2 = sS[w][2][j], g3 = sS[w][3][j];
            c0.x = fmaf(g0, wp.x, c0.x); c0.y = fmaf(g0, wp.y, c0.y);
            c1.x = fmaf(g1, wp.x, c1.x); c1.y = fmaf(g1, wp.y, c1.y);
            c2.x = fmaf(g2, wp.x, c2.x); c2.y = fmaf(g2, wp.y, c2.y);
            c3.x = fmaf(g3, wp.x, c3.x); c3.y = fmaf(g3, wp.y, c3.y);
        }
        __syncwarp();
        *(float2*)&sS[w][0][f0] = make_float2(mishf(c0.x), mishf(c0.y));
        *(float2*)&sS[w][1][f0] = make_float2(mishf(c1.x), mishf(c1.y));
        *(float2*)&sS[w][2][f0] = make_float2(mishf(c2.x), mishf(c2.y));
        *(float2*)&sS[w][3][f0] = make_float2(mishf(c3.x), mishf(c3.y));
        __syncwarp();
        bx = sb2[f0]; by = sb2[f0 + 1];
        float2 d0 = {bx, by}, d1 = {bx, by}, d2 = {bx, by}, d3 = {bx, by};
#pragma unroll 8
        for (int j = 0; j < DD; j++) {
            float2 wp = sW2v[j * 32 + lane];
            float g0 = sS[w][0][j], g1 = sS[w][1][j], g2 = sS[w][2][j], g3 = sS[w][3][j];
            d0.x = fmaf(g0, wp.x, d0.x); d0.y = fmaf(g0, wp.y, d0.y);
            d1.x = fmaf(g1, wp.x, d1.x); d1.y = fmaf(g1, wp.y, d1.y);
            d2.x = fmaf(g2, wp.x, d2.x); d2.y = fmaf(g2, wp.y, d2.y);
            d3.x = fmaf(g3, wp.x, d3.x); d3.y = fmaf(g3, wp.y, d3.y);
        }
        if (base + 0 < NN) { *(float2*)(g_xproj + (size_t)(base + 0) * DD + f0) = d0; *(float2*)(g_h + (size_t)(base + 0) * DD + f0) = d0; }
        if (base + 1 < NN) { *(float2*)(g_xproj + (size_t)(base + 1) * DD + f0) = d1; *(float2*)(g_h + (size_t)(base + 1) * DD + f0) = d1; }
        if (base + 2 < NN) { *(float2*)(g_xproj + (size_t)(base + 2) * DD + f0) = d2; *(float2*)(g_h + (size_t)(base + 2) * DD + f0) = d2; }
        if (base + 3 < NN) { *(float2*)(g_xproj + (size_t)(base + 3) * DD + f0) = d3; *(float2*)(g_h + (size_t)(base + 3) * DD + f0) = d3; }
        __syncwarp();
    }
}

// ---------------- dropout mask: JAX threefry, PARTITIONABLE path ----------------
// Modern JAX (jax_threefry_partitionable=True, default since ~jax 0.5):
// bits[m] = o0 ^ o1 where (o0,o1) = threefry2x32(key, (hi64(m)=0, lo64(m)=m)),
// flat m = r*N + n for shape (R, N). fold_in is unchanged (not via random_bits).
__global__ void k_mask(uint32_t k0, uint32_t k1) {
    int n = blockIdx.x * blockDim.x + threadIdx.x;
    if (blockIdx.x == 0 && threadIdx.x < DD) { g_bnsum[threadIdx.x] = 0.f; g_bnsq[threadIdx.x] = 0.f; }
    if (n >= NN) return;
    uint32_t o0, o1;
    unsigned byte = 0;
    tf2x32(k0, k1, 0u, (uint32_t)(n),          o0, o1); byte |= keepbit(o0 ^ o1);
    tf2x32(k0, k1, 0u, (uint32_t)(n + NN),     o0, o1); byte |= keepbit(o0 ^ o1) << 1;
    tf2x32(k0, k1, 0u, (uint32_t)(n + 2 * NN), o0, o1); byte |= keepbit(o0 ^ o1) << 2;
    tf2x32(k0, k1, 0u, (uint32_t)(n + 3 * NN), o0, o1); byte |= keepbit(o0 ^ o1) << 3;
    g_keep[n] = (unsigned char)byte;
}

// ---------------- fused layer: aggregate + 2 GEMVs (x4 replicas) + mean + residual + bn-stats ----------------
__global__ void __launch_bounds__(256) k_layer(const float* __restrict__ W1, const float* __restrict__ b1,
                                               const float* __restrict__ W2, const float* __restrict__ b2) {
    __shared__ float sW1[DD * DD], sW2[DD * DD], sb1[DD], sb2[DD];
    __shared__ float sHG[8][4][DD];
    __shared__ float sR[8][DD];
    int tid = threadIdx.x, lane = tid & 31, w = tid >> 5;
    for (int i = tid; i < DD * DD; i += 256) { sW1[i] = W1[i]; sW2[i] = W2[i]; }
    if (tid < DD) { sb1[tid] = b1[tid]; sb2[tid] = b2[tid]; }
    __syncthreads();
    const float2* sW1v = (const float2*)sW1;
    const float2* sW2v = (const float2*)sW2;
    int f0 = lane * 2;
    float bs0 = 0.f, bs1 = 0.f, bq0 = 0.f, bq1 = 0.f;
    int gw = blockIdx.x * 8 + w;
    int stride = gridDim.x * 8;
    for (int n = gw; n < NN; n += stride) {
        float2 hn = *(const float2*)(g_h + (size_t)n * DD + f0);
        unsigned kbn = g_keep[n];
        float2 a0 = {0, 0}, a1 = {0, 0}, a2 = {0, 0}, a3 = {0, 0};
        int e = g_rowptr[n], eend = g_rowptr[n + 1];
        if (e < eend) {
            int s = g_srcsorted[e];
            for (; e < eend; ) {
                int snext = (e + 1 < eend) ? g_srcsorted[e + 1] : 0;
                unsigned kb = g_keep[s];
                float2 v = *(const float2*)(g_h + (size_t)s * DD + f0);
                if (kb & 1u) { a0.x += v.x; a0.y += v.y; }
                if (kb & 2u) { a1.x += v.x; a1.y += v.y; }
                if (kb & 4u) { a2.x += v.x; a2.y += v.y; }
                if (kb & 8u) { a3.x += v.x; a3.y += v.y; }
                s = snext; e++;
            }
        }
        if (kbn & 1u) { a0.x += hn.x; a0.y += hn.y; }
        if (kbn & 2u) { a1.x += hn.x; a1.y += hn.y; }
        if (kbn & 4u) { a2.x += hn.x; a2.y += hn.y; }
        if (kbn & 8u) { a3.x += hn.x; a3.y += hn.y; }
        *(float2*)&sHG[w][0][f0] = a0;
        *(float2*)&sHG[w][1][f0] = a1;
        *(float2*)&sHG[w][2][f0] = a2;
        *(float2*)&sHG[w][3][f0] = a3;
        __syncwarp();
        float bx = sb1[f0], by = sb1[f0 + 1];
        float2 c0 = {bx, by}, c1 = {bx, by}, c2 = {bx, by}, c3 = {bx, by};
#pragma unroll 8
        for (int j = 0; j < DD; j++) {
            float2 wp = sW1v[j * 32 + lane];
            float g0 = sHG[w][0][j], g1 = sHG[w][1][j], g2 = sHG[w][2][j], g3 = sHG[w][3][j];
            c0.x = fmaf(g0, wp.x, c0.x); c0.y = fmaf(g0, wp.y, c0.y);
            c1.x = fmaf(g1, wp.x, c1.x); c1.y = fmaf(g1, wp.y, c1.y);
            c2.x = fmaf(g2, wp.x, c2.x); c2.y = fmaf(g2, wp.y, c2.y);
            c3.x = fmaf(g3, wp.x, c3.x); c3.y = fmaf(g3, wp.y, c3.y);
        }
        __syncwarp();
        *(float2*)&sHG[w][0][f0] = make_float2(mishf(c0.x), mishf(c0.y));
        *(float2*)&sHG[w][1][f0] = make_float2(mishf(c1.x), mishf(c1.y));
        *(float2*)&sHG[w][2][f0] = make_float2(mishf(c2.x), mishf(c2.y));
        *(float2*)&sHG[w][3][f0] = make_float2(mishf(c3.x), mishf(c3.y));
        __syncwarp();
        bx = sb2[f0]; by = sb2[f0 + 1];
        float2 d0 = {bx, by}, d1 = {bx, by}, d2 = {bx, by}, d3 = {bx, by};
#pragma unroll 8
        for (int j = 0; j < DD; j++) {
            float2 wp = sW2v[j * 32 + lane];
            float g0 = sHG[w][0][j], g1 = sHG[w][1][j], g2 = sHG[w][2][j], g3 = sHG[w][3][j];
            d0.x = fmaf(g0, wp.x, d0.x); d0.y = fmaf(g0, wp.y, d0.y);
            d1.x = fmaf(g1, wp.x, d1.x); d1.y = fmaf(g1, wp.y, d1.y);
            d2.x = fmaf(g2, wp.x, d2.x); d2.y = fmaf(g2, wp.y, d2.y);
            d3.x = fmaf(g3, wp.x, d3.x); d3.y = fmaf(g3, wp.y, d3.y);
        }
        float px = 0.25f * (d0.x + d1.x + d2.x + d3.x) + hn.x;
        float py = 0.25f * (d0.y + d1.y + d2.y + d3.y) + hn.y;
        *(float2*)(g_hpre + (size_t)n * DD + f0) = make_float2(px, py);
        bs0 += px; bs1 += py; bq0 += px * px; bq1 += py * py;
        __syncwarp();
    }
    // block-level bn reduction, one atomic per feature per block
    __syncthreads();
    sR[w][f0] = bs0; sR[w][f0 + 1] = bs1;
    __syncthreads();
    if (tid < DD) {
        float s = 0.f;
        for (int k = 0; k < 8; k++) s += sR[k][tid];
        atomicAdd(&g_bnsum[tid], s);
    }
    __syncthreads();
    sR[w][f0] = bq0; sR[w][f0 + 1] = bq1;
    __syncthreads();
    if (tid < DD) {
        float s = 0.f;
        for (int k = 0; k < 8; k++) s += sR[k][tid];
        atomicAdd(&g_bnsq[tid], s);
    }
}

__global__ void k_bnfin() {
    int f = threadIdx.x;
    float m = g_bnsum[f] * (1.0f / (float)NN);
    float q = g_bnsq[f] * (1.0f / (float)NN);
    g_mu[f] = m;
    g_inv[f] = rsqrtf(q - m * m + 1e-5f);
}

__global__ void k_norm(int last, float* __restrict__ out) {
    int i = blockIdx.x * blockDim.x + threadIdx.x;
    if (i >= NN * DD) return;
    int f = i & (DD - 1);
    float v = (g_hpre[i] - g_mu[f]) * g_inv[f];
    v = mishf(v);
    g_h[i] = v;
    if (last) out[i] = g_xproj[i] + v;
}

// ---------------- launcher ----------------
extern "C" void kernel_launch(void* const* d_in, const int* in_sizes, int n_in,
                              void* d_out, int out_size) {
    const float* x   = (const float*)d_in[0];
    const void*  ei  = d_in[1];
    const float* nW1 = (const float*)d_in[2];
    const float* nb1 = (const float*)d_in[3];
    const float* nW2 = (const float*)d_in[4];
    const float* nb2 = (const float*)d_in[5];
    const float* cW1 = (const float*)d_in[6];
    const float* cb1 = (const float*)d_in[7];
    const float* cW2 = (const float*)d_in[8];
    const float* cb2 = (const float*)d_in[9];
    float* out = (float*)d_out;

    k_detect<<<1, 256>>>((const unsigned long long*)ei);
    k_zerodeg<<<(NN + 255) / 256, 256>>>();
    k_convert<<<(EE + 255) / 256, 256>>>(ei);
    k_scan<<<1, 1024>>>();
    k_scatter<<<(EE + 255) / 256, 256>>>();
    k_xproj<<<592, 256>>>(x, nW1, nb1, nW2, nb2);

    for (int i = 0; i < 3; i++) {
        uint32_t o0, o1;
        tf2x32(0u, 42u, 0u, (uint32_t)i, o0, o1);   // fold_in(key(42), i) on host (unchanged by partitionable flag)
        k_mask<<<(NN + 255) / 256, 256>>>(o0, o1);
        k_layer<<<592, 256>>>(cW1 + i * DD * DD, cb1 + i * DD, cW2 + i * DD * DD, cb2 + i * DD);
        k_bnfin<<<1, 64>>>();
        k_norm<<<(NN * DD + 255) / 256, 256>>>(i == 2 ? 1 : 0, out);
    }
}

// round 15
// speedup vs baseline: 1.0805x; 1.0805x over previous
#include <cuda_runtime.h>
#include <cstdint>

#define NN 50000
#define EE 800000
#define DD 64
#define SCAN_B 256
#define SCAN_NB ((NN + SCAN_B - 1) / SCAN_B)   /* 196 */

// ---------------- device scratch (static: no allocation allowed) ----------------
__device__ int g_flag64;
__device__ int g_src[EE];
__device__ int g_dst[EE];
__device__ int g_deg[NN];
__device__ int g_rowptr[NN + 1];
__device__ int g_tail[NN];
__device__ int g_partial[SCAN_NB];
__device__ int g_srcsorted[EE];
__device__ float g_h[NN * DD];
__device__ float g_hpre[NN * DD];
__device__ float g_xproj[NN * DD];
__device__ unsigned char g_keep3[3 * NN];
__device__ float g_bnsum2[3][DD];
__device__ float g_bnsq2[3][DD];

// ---------------- threefry2x32 (matches JAX exactly) ----------------
__host__ __device__ __forceinline__ void tf2x32(uint32_t k0, uint32_t k1,
                                                uint32_t x0, uint32_t x1,
                                                uint32_t& o0, uint32_t& o1) {
    uint32_t ks2 = k0 ^ k1 ^ 0x1BD11BDAu;
    x0 += k0; x1 += k1;
#define TF_RND(r) { x0 += x1; x1 = (x1 << (r)) | (x1 >> (32 - (r))); x1 ^= x0; }
    TF_RND(13) TF_RND(15) TF_RND(26) TF_RND(6)   x0 += k1;  x1 += ks2 + 1u;
    TF_RND(17) TF_RND(29) TF_RND(16) TF_RND(24)  x0 += ks2; x1 += k0 + 2u;
    TF_RND(13) TF_RND(15) TF_RND(26) TF_RND(6)   x0 += k0;  x1 += k1 + 3u;
    TF_RND(17) TF_RND(29) TF_RND(16) TF_RND(24)  x0 += k1;  x1 += ks2 + 4u;
    TF_RND(13) TF_RND(15) TF_RND(26) TF_RND(6)   x0 += ks2; x1 += k0 + 5u;
#undef TF_RND
    o0 = x0; o1 = x1;
}

__device__ __forceinline__ unsigned keepbit(uint32_t bits) {
    // JAX uniform: bitcast(bits>>9 | 0x3f800000) - 1.0 in [0,1); drop iff u < p
    float u = __uint_as_float((bits >> 9) | 0x3f800000u) - 1.0f;
    return (u < 0.2f) ? 0u : 1u;
}

__device__ __forceinline__ float mishf(float x) {
    float sp = fmaxf(x, 0.0f) + log1pf(expf(-fabsf(x)));
    return x * tanhf(sp);
}

// ---------------- preprocessing ----------------
__global__ void k_detect(const unsigned long long* ei) {
    __shared__ int any;
    if (threadIdx.x == 0) any = 0;
    __syncthreads();
    int nz = 0;
    for (int q = 0; q < 4; q++) {
        unsigned long long v = ei[threadIdx.x * 4 + q];
        if ((v >> 32) != 0ull) nz = 1;
    }
    if (nz) any = 1;
    __syncthreads();
    if (threadIdx.x == 0) g_flag64 = any ? 0 : 1;
}

__global__ void k_zerodeg() {
    int i = blockIdx.x * blockDim.x + threadIdx.x;
    if (i < NN) g_deg[i] = 0;
}

__global__ void k_convert(const void* ei) {
    int e = blockIdx.x * blockDim.x + threadIdx.x;
    if (e >= EE) return;
    int s, d;
    if (g_flag64) {
        const long long* p = (const long long*)ei;
        s = (int)p[e]; d = (int)p[EE + e];
    } else {
        const int* p = (const int*)ei;
        s = p[e]; d = p[EE + e];
    }
    g_src[e] = s; g_dst[e] = d;
    atomicAdd(&g_deg[d], 1);
}

// 3-phase multi-block exclusive scan of g_deg -> g_rowptr/g_tail
__global__ void k_scan1() {   // per-block local exclusive scan + block totals
    __shared__ int swarp[8];
    int tid = threadIdx.x, lane = tid & 31, wid = tid >> 5;
    int i = blockIdx.x * SCAN_B + tid;
    int orig = (i < NN) ? g_deg[i] : 0;
    int v = orig;
#pragma unroll
    for (int d = 1; d < 32; d <<= 1) {
        int t = __shfl_up_sync(0xffffffffu, v, d);
        if (lane >= d) v += t;
    }
    if (lane == 31) swarp[wid] = v;
    __syncthreads();
    if (wid == 0) {
        int w = (lane < 8) ? swarp[lane] : 0;
#pragma unroll
        for (int d = 1; d < 8; d <<= 1) {
            int t = __shfl_up_sync(0xffffffffu, w, d);
            if (lane >= d) w += t;
        }
        if (lane < 8) swarp[lane] = w;
    }
    __syncthreads();
    int add = wid ? swarp[wid - 1] : 0;
    if (i < NN) g_rowptr[i] = v - orig + add;   // block-local exclusive
    if (tid == 0) g_partial[blockIdx.x] = swarp[7];
}

__global__ void k_scan2() {   // 1 block: exclusive scan of SCAN_NB partials
    __shared__ int swarp[8];
    int tid = threadIdx.x, lane = tid & 31, wid = tid >> 5;
    int orig = (tid < SCAN_NB) ? g_partial[tid] : 0;
    int v = orig;
#pragma unroll
    for (int d = 1; d < 32; d <<= 1) {
        int t = __shfl_up_sync(0xffffffffu, v, d);
        if (lane >= d) v += t;
    }
    if (lane == 31) swarp[wid] = v;
    __syncthreads();
    if (wid == 0) {
        int w = (lane < 8) ? swarp[lane] : 0;
#pragma unroll
        for (int d = 1; d < 8; d <<= 1) {
            int t = __shfl_up_sync(0xffffffffu, w, d);
            if (lane >= d) w += t;
        }
        if (lane < 8) swarp[lane] = w;
    }
    __syncthreads();
    int add = wid ? swarp[wid - 1] : 0;
    if (tid < SCAN_NB) g_partial[tid] = v - orig + add;
    if (tid == 0) g_rowptr[NN] = swarp[7];   // total == EE
}

__global__ void k_scan3() {   // add block offsets; init tails
    int i = blockIdx.x * blockDim.x + threadIdx.x;
    if (i >= NN) return;
    int r = g_rowptr[i] + g_partial[i / SCAN_B];
    g_rowptr[i] = r;
    g_tail[i] = r;
}

__global__ void k_scatter() {
    int e = blockIdx.x * blockDim.x + threadIdx.x;
    if (e >= EE) return;
    int d = g_dst[e];
    int p = atomicAdd(&g_tail[d], 1);
    g_srcsorted[p] = g_src[e];
}

// ---------------- all 3 layers' dropout masks (partitionable threefry) + bn zero ----------------
__global__ void k_masks(uint32_t k00, uint32_t k01, uint32_t k10, uint32_t k11,
                        uint32_t k20, uint32_t k21) {
    int n = blockIdx.x * blockDim.x + threadIdx.x;
    if (blockIdx.x == 0 && threadIdx.x < 3 * DD) {
        ((float*)g_bnsum2)[threadIdx.x] = 0.f;
        ((float*)g_bnsq2)[threadIdx.x] = 0.f;
    }
    if (n >= NN) return;
    uint32_t o0, o1;
    uint32_t ks[6] = {k00, k01, k10, k11, k20, k21};
#pragma unroll
    for (int L = 0; L < 3; L++) {
        unsigned byte = 0;
        tf2x32(ks[2 * L], ks[2 * L + 1], 0u, (uint32_t)(n),          o0, o1); byte |= keepbit(o0 ^ o1);
        tf2x32(ks[2 * L], ks[2 * L + 1], 0u, (uint32_t)(n + NN),     o0, o1); byte |= keepbit(o0 ^ o1) << 1;
        tf2x32(ks[2 * L], ks[2 * L + 1], 0u, (uint32_t)(n + 2 * NN), o0, o1); byte |= keepbit(o0 ^ o1) << 2;
        tf2x32(ks[2 * L], ks[2 * L + 1], 0u, (uint32_t)(n + 3 * NN), o0, o1); byte |= keepbit(o0 ^ o1) << 3;
        g_keep3[L * NN + n] = (unsigned char)byte;
    }
}

// ---------------- x_proj: mish(x@W1+b1)@W2+b2 ; 4 rows per warp ----------------
__global__ void __launch_bounds__(256) k_xproj(const float* __restrict__ x,
                                               const float* __restrict__ W1, const float* __restrict__ b1,
                                               const float* __restrict__ W2, const float* __restrict__ b2) {
    __shared__ float sW1[DD * DD], sW2[DD * DD], sb1[DD], sb2[DD];
    __shared__ float sS[8][4][DD];
    int tid = threadIdx.x, lane = tid & 31, w = tid >> 5;
    for (int i = tid; i < DD * DD; i += 256) { sW1[i] = W1[i]; sW2[i] = W2[i]; }
    if (tid < DD) { sb1[tid] = b1[tid]; sb2[tid] = b2[tid]; }
    __syncthreads();
    const float2* sW1v = (const float2*)sW1;
    const float2* sW2v = (const float2*)sW2;
    int f0 = lane * 2;
    int gw = blockIdx.x * 8 + w;
    int stride = gridDim.x * 8 * 4;
    for (int base = gw * 4; base < NN; base += stride) {
#pragma unroll
        for (int q = 0; q < 4; q++) {
            int n = base + q;
            float2 v = make_float2(0.f, 0.f);
            if (n < NN) v = *(const float2*)(x + (size_t)n * DD + f0);
            *(float2*)&sS[w][q][f0] = v;
        }
        __syncwarp();
        float bx = sb1[f0], by = sb1[f0 + 1];
        float2 c0 = {bx, by}, c1 = {bx, by}, c2 = {bx, by}, c3 = {bx, by};
#pragma unroll 8
        for (int j = 0; j < DD; j++) {
            float2 wp = sW1v[j * 32 + lane];
            float g0 = sS[w][0][j], g1 = sS[w][1][j], g2 = sS[w][2][j], g3 = sS[w][3][j];
            c0.x = fmaf(g0, wp.x, c0.x); c0.y = fmaf(g0, wp.y, c0.y);
            c1.x = fmaf(g1, wp.x, c1.x); c1.y = fmaf(g1, wp.y, c1.y);
            c2.x = fmaf(g2, wp.x, c2.x); c2.y = fmaf(g2, wp.y, c2.y);
            c3.x = fmaf(g3, wp.x, c3.x); c3.y = fmaf(g3, wp.y, c3.y);
        }
        __syncwarp();
        *(float2*)&sS[w][0][f0] = make_float2(mishf(c0.x), mishf(c0.y));
        *(float2*)&sS[w][1][f0] = make_float2(mishf(c1.x), mishf(c1.y));
        *(float2*)&sS[w][2][f0] = make_float2(mishf(c2.x), mishf(c2.y));
        *(float2*)&sS[w][3][f0] = make_float2(mishf(c3.x), mishf(c3.y));
        __syncwarp();
        bx = sb2[f0]; by = sb2[f0 + 1];
        float2 d0 = {bx, by}, d1 = {bx, by}, d2 = {bx, by}, d3 = {bx, by};
#pragma unroll 8
        for (int j = 0; j < DD; j++) {
            float2 wp = sW2v[j * 32 + lane];
            float g0 = sS[w][0][j], g1 = sS[w][1][j], g2 = sS[w][2][j], g3 = sS[w][3][j];
            d0.x = fmaf(g0, wp.x, d0.x); d0.y = fmaf(g0, wp.y, d0.y);
            d1.x = fmaf(g1, wp.x, d1.x); d1.y = fmaf(g1, wp.y, d1.y);
            d2.x = fmaf(g2, wp.x, d2.x); d2.y = fmaf(g2, wp.y, d2.y);
            d3.x = fmaf(g3, wp.x, d3.x); d3.y = fmaf(g3, wp.y, d3.y);
        }
        if (base + 0 < NN) { *(float2*)(g_xproj + (size_t)(base + 0) * DD + f0) = d0; *(float2*)(g_h + (size_t)(base + 0) * DD + f0) = d0; }
        if (base + 1 < NN) { *(float2*)(g_xproj + (size_t)(base + 1) * DD + f0) = d1; *(float2*)(g_h + (size_t)(base + 1) * DD + f0) = d1; }
        if (base + 2 < NN) { *(float2*)(g_xproj + (size_t)(base + 2) * DD + f0) = d2; *(float2*)(g_h + (size_t)(base + 2) * DD + f0) = d2; }
        if (base + 3 < NN) { *(float2*)(g_xproj + (size_t)(base + 3) * DD + f0) = d3; *(float2*)(g_h + (size_t)(base + 3) * DD + f0) = d3; }
        __syncwarp();
    }
}

// ---------------- fused layer: aggregate + 2 GEMVs (x4 replicas) + mean + residual + bn-stats ----------------
__global__ void __launch_bounds__(256) k_layer(int layer,
                                               const float* __restrict__ W1, const float* __restrict__ b1,
                                               const float* __restrict__ W2, const float* __restrict__ b2) {
    __shared__ float sW1[DD * DD], sW2[DD * DD], sb1[DD], sb2[DD];
    __shared__ float sHG[8][4][DD];
    __shared__ float sR[8][DD];
    int tid = threadIdx.x, lane = tid & 31, w = tid >> 5;
    const unsigned char* __restrict__ keep = g_keep3 + layer * NN;
    for (int i = tid; i < DD * DD; i += 256) { sW1[i] = W1[i]; sW2[i] = W2[i]; }
    if (tid < DD) { sb1[tid] = b1[tid]; sb2[tid] = b2[tid]; }
    __syncthreads();
    const float2* sW1v = (const float2*)sW1;
    const float2* sW2v = (const float2*)sW2;
    int f0 = lane * 2;
    float bs0 = 0.f, bs1 = 0.f, bq0 = 0.f, bq1 = 0.f;
    int gw = blockIdx.x * 8 + w;
    int stride = gridDim.x * 8;
    for (int n = gw; n < NN; n += stride) {
        float2 hn = *(const float2*)(g_h + (size_t)n * DD + f0);
        unsigned kbn = keep[n];
        float2 a0 = {0, 0}, a1 = {0, 0}, a2 = {0, 0}, a3 = {0, 0};
        int e = g_rowptr[n], eend = g_rowptr[n + 1];
        for (; e < eend; e++) {
            int s = g_srcsorted[e];
            unsigned kb = keep[s];
            float2 v = *(const float2*)(g_h + (size_t)s * DD + f0);
            if (kb & 1u) { a0.x += v.x; a0.y += v.y; }
            if (kb & 2u) { a1.x += v.x; a1.y += v.y; }
            if (kb & 4u) { a2.x += v.x; a2.y += v.y; }
            if (kb & 8u) { a3.x += v.x; a3.y += v.y; }
        }
        if (kbn & 1u) { a0.x += hn.x; a0.y += hn.y; }
        if (kbn & 2u) { a1.x += hn.x; a1.y += hn.y; }
        if (kbn & 4u) { a2.x += hn.x; a2.y += hn.y; }
        if (kbn & 8u) { a3.x += hn.x; a3.y += hn.y; }
        *(float2*)&sHG[w][0][f0] = a0;
        *(float2*)&sHG[w][1][f0] = a1;
        *(float2*)&sHG[w][2][f0] = a2;
        *(float2*)&sHG[w][3][f0] = a3;
        __syncwarp();
        float bx = sb1[f0], by = sb1[f0 + 1];
        float2 c0 = {bx, by}, c1 = {bx, by}, c2 = {bx, by}, c3 = {bx, by};
#pragma unroll 8
        for (int j = 0; j < DD; j++) {
            float2 wp = sW1v[j * 32 + lane];
            float g0 = sHG[w][0][j], g1 = sHG[w][1][j], g2 = sHG[w][2][j], g3 = sHG[w][3][j];
            c0.x = fmaf(g0, wp.x, c0.x); c0.y = fmaf(g0, wp.y, c0.y);
            c1.x = fmaf(g1, wp.x, c1.x); c1.y = fmaf(g1, wp.y, c1.y);
            c2.x = fmaf(g2, wp.x, c2.x); c2.y = fmaf(g2, wp.y, c2.y);
            c3.x = fmaf(g3, wp.x, c3.x); c3.y = fmaf(g3, wp.y, c3.y);
        }
        __syncwarp();
        *(float2*)&sHG[w][0][f0] = make_float2(mishf(c0.x), mishf(c0.y));
        *(float2*)&sHG[w][1][f0] = make_float2(mishf(c1.x), mishf(c1.y));
        *(float2*)&sHG[w][2][f0] = make_float2(mishf(c2.x), mishf(c2.y));
        *(float2*)&sHG[w][3][f0] = make_float2(mishf(c3.x), mishf(c3.y));
        __syncwarp();
        bx = sb2[f0]; by = sb2[f0 + 1];
        float2 d0 = {bx, by}, d1 = {bx, by}, d2 = {bx, by}, d3 = {bx, by};
#pragma unroll 8
        for (int j = 0; j < DD; j++) {
            float2 wp = sW2v[j * 32 + lane];
            float g0 = sHG[w][0][j], g1 = sHG[w][1][j], g2 = sHG[w][2][j], g3 = sHG[w][3][j];
            d0.x = fmaf(g0, wp.x, d0.x); d0.y = fmaf(g0, wp.y, d0.y);
            d1.x = fmaf(g1, wp.x, d1.x); d1.y = fmaf(g1, wp.y, d1.y);
            d2.x = fmaf(g2, wp.x, d2.x); d2.y = fmaf(g2, wp.y, d2.y);
            d3.x = fmaf(g3, wp.x, d3.x); d3.y = fmaf(g3, wp.y, d3.y);
        }
        float px = 0.25f * (d0.x + d1.x + d2.x + d3.x) + hn.x;
        float py = 0.25f * (d0.y + d1.y + d2.y + d3.y) + hn.y;
        *(float2*)(g_hpre + (size_t)n * DD + f0) = make_float2(px, py);
        bs0 += px; bs1 += py; bq0 += px * px; bq1 += py * py;
        __syncwarp();
    }
    __syncthreads();
    sR[w][f0] = bs0; sR[w][f0 + 1] = bs1;
    __syncthreads();
    if (tid < DD) {
        float s = 0.f;
        for (int k = 0; k < 8; k++) s += sR[k][tid];
        atomicAdd(&g_bnsum2[layer][tid], s);
    }
    __syncthreads();
    sR[w][f0] = bq0; sR[w][f0 + 1] = bq1;
    __syncthreads();
    if (tid < DD) {
        float s = 0.f;
        for (int k = 0; k < 8; k++) s += sR[k][tid];
        atomicAdd(&g_bnsq2[layer][tid], s);
    }
}

// ---------------- bn finalize folded into norm: each block computes mu/inv from reduced sums ----------------
__global__ void k_norm(int layer, int last, float* __restrict__ out) {
    __shared__ float smu[DD], sinv[DD];
    int tid = threadIdx.x;
    if (tid < DD) {
        float m = g_bnsum2[layer][tid] * (1.0f / (float)NN);
        float q = g_bnsq2[layer][tid] * (1.0f / (float)NN);
        smu[tid] = m;
        sinv[tid] = rsqrtf(q - m * m + 1e-5f);
    }
    __syncthreads();
    int i = blockIdx.x * blockDim.x + tid;
    if (i >= NN * DD) return;
    int f = i & (DD - 1);
    float v = (g_hpre[i] - smu[f]) * sinv[f];
    v = mishf(v);
    g_h[i] = v;
    if (last) out[i] = g_xproj[i] + v;
}

// ---------------- launcher ----------------
extern "C" void kernel_launch(void* const* d_in, const int* in_sizes, int n_in,
                              void* d_out, int out_size) {
    const float* x   = (const float*)d_in[0];
    const void*  ei  = d_in[1];
    const float* nW1 = (const float*)d_in[2];
    const float* nb1 = (const float*)d_in[3];
    const float* nW2 = (const float*)d_in[4];
    const float* nb2 = (const float*)d_in[5];
    const float* cW1 = (const float*)d_in[6];
    const float* cb1 = (const float*)d_in[7];
    const float* cW2 = (const float*)d_in[8];
    const float* cb2 = (const float*)d_in[9];
    float* out = (float*)d_out;

    k_detect<<<1, 256>>>((const unsigned long long*)ei);
    k_zerodeg<<<(NN + 255) / 256, 256>>>();
    k_convert<<<(EE + 255) / 256, 256>>>(ei);
    k_scan1<<<SCAN_NB, SCAN_B>>>();
    k_scan2<<<1, 256>>>();
    k_scan3<<<(NN + 255) / 256, 256>>>();
    k_scatter<<<(EE + 255) / 256, 256>>>();

    uint32_t k[6];
    for (int i = 0; i < 3; i++)
        tf2x32(0u, 42u, 0u, (uint32_t)i, k[2 * i], k[2 * i + 1]);   // fold_in(key(42), i)
    k_masks<<<(NN + 255) / 256, 256>>>(k[0], k[1], k[2], k[3], k[4], k[5]);

    k_xproj<<<592, 256>>>(x, nW1, nb1, nW2, nb2);

    for (int i = 0; i < 3; i++) {
        k_layer<<<592, 256>>>(i, cW1 + i * DD * DD, cb1 + i * DD, cW2 + i * DD * DD, cb2 + i * DD);
        k_norm<<<(NN * DD + 255) / 256, 256>>>(i, i == 2 ? 1 : 0, out);
    }
}